// round 1
// baseline (speedup 1.0000x reference)
#include <cuda_runtime.h>
#include <cuda_bf16.h>
#include <math.h>

// ----------------------------------------------------------------------------
// CSwinAttention: x(8,4096,512) -> qkv GEMM -> stripe attention (h/v halves,
// ss=8, 16 heads, hd=32) + LePE depthwise 3x3 -> proj GEMM + bias.
// Sizes are fixed by the problem; hardcoded for speed.
// ----------------------------------------------------------------------------

#define Bc     8
#define Hc     64
#define Wc     64
#define Lc     4096          // H*W
#define Cc     512
#define Mrows  32768         // B*L
#define QKVN   1536
#define HALF   256
#define SS     8
#define HD     32

// Scratch (allocation-free rule: __device__ globals)
__device__ float g_qkv[(size_t)Mrows * QKVN];   // ~201 MB
__device__ float g_attn[(size_t)Mrows * Cc];    // ~67 MB

// ----------------------------------------------------------------------------
// SGEMM NT: C[M,N] = A[M,K] * B[N,K]^T (+ bias). A,B row-major K-contiguous.
// 128x128 tile, BK=16, 256 threads, 8x8 micro-tile per thread.
// Requires M%128==0, N%128==0, K%16==0 (true here).
// ----------------------------------------------------------------------------
#define BM 128
#define BN 128
#define BK 16
#define TM 8
#define TN 8

__global__ __launch_bounds__(256, 2) void sgemm_nt(
    const float* __restrict__ A, const float* __restrict__ Bm,
    const float* __restrict__ bias, float* __restrict__ C,
    int M, int N, int K)
{
    __shared__ float As[BK][BM];
    __shared__ float Bs[BK][BN];

    const int tid = threadIdx.x;
    const int tx = tid & 15;
    const int ty = tid >> 4;
    const int row0 = blockIdx.y * BM;
    const int col0 = blockIdx.x * BN;

    const float* Aptr = A + (size_t)row0 * K;
    const float* Bptr = Bm + (size_t)col0 * K;

    float acc[TM][TN];
    #pragma unroll
    for (int i = 0; i < TM; ++i)
        #pragma unroll
        for (int j = 0; j < TN; ++j) acc[i][j] = 0.f;

    for (int k0 = 0; k0 < K; k0 += BK) {
        // Stage A and B tiles (each 128x16 floats = 512 float4; 2 per thread)
        #pragma unroll
        for (int it = 0; it < 2; ++it) {
            int lid = tid + it * 256;
            int r  = lid >> 2;          // 0..127
            int c4 = (lid & 3) << 2;    // 0,4,8,12
            float4 va = *reinterpret_cast<const float4*>(Aptr + (size_t)r * K + k0 + c4);
            As[c4 + 0][r] = va.x; As[c4 + 1][r] = va.y;
            As[c4 + 2][r] = va.z; As[c4 + 3][r] = va.w;
            float4 vb = *reinterpret_cast<const float4*>(Bptr + (size_t)r * K + k0 + c4);
            Bs[c4 + 0][r] = vb.x; Bs[c4 + 1][r] = vb.y;
            Bs[c4 + 2][r] = vb.z; Bs[c4 + 3][r] = vb.w;
        }
        __syncthreads();

        #pragma unroll
        for (int kk = 0; kk < BK; ++kk) {
            float a_frag[TM], b_frag[TN];
            #pragma unroll
            for (int i = 0; i < TM; ++i) a_frag[i] = As[kk][ty * TM + i];
            #pragma unroll
            for (int j = 0; j < TN; ++j) b_frag[j] = Bs[kk][tx * TN + j];
            #pragma unroll
            for (int i = 0; i < TM; ++i)
                #pragma unroll
                for (int j = 0; j < TN; ++j)
                    acc[i][j] += a_frag[i] * b_frag[j];
        }
        __syncthreads();
    }

    #pragma unroll
    for (int i = 0; i < TM; ++i) {
        int r = row0 + ty * TM + i;
        #pragma unroll
        for (int j = 0; j < TN; j += 4) {
            int cI = col0 + tx * TN + j;
            float4 v;
            v.x = acc[i][j + 0]; v.y = acc[i][j + 1];
            v.z = acc[i][j + 2]; v.w = acc[i][j + 3];
            if (bias) {
                v.x += bias[cI + 0]; v.y += bias[cI + 1];
                v.z += bias[cI + 2]; v.w += bias[cI + 3];
            }
            *reinterpret_cast<float4*>(C + (size_t)r * N + cI) = v;
        }
    }
}

// ----------------------------------------------------------------------------
// Stripe attention + LePE.
// Grid: 8192 blocks. blocks [0,4096): axis 0 (horizontal stripes, heads 0..7,
// channels 0..255). blocks [4096,8192): axis 1 (vertical, heads 8..15,
// channels 256..511). One block = one window (8 positions x 256 half-channels),
// one warp = one head.
// ----------------------------------------------------------------------------
#define SROW 264   // padded smem row stride (breaks bank conflicts)

__global__ __launch_bounds__(256) void stripe_attn_kernel(
    const float* __restrict__ qkv,
    const float* __restrict__ lepe_h,
    const float* __restrict__ lepe_v,
    float* __restrict__ out)
{
    __shared__ float qs[SS * SROW];
    __shared__ float ks[SS * SROW];
    __shared__ float vs[SS * SROW];
    __shared__ float Ssm[8][64];

    const int blk  = blockIdx.x;
    const int axis = (blk >= 4096) ? 1 : 0;
    const int wb   = blk & 4095;
    const int tid  = threadIdx.x;
    const int warp = tid >> 5;
    const int lane = tid & 31;

    int b, h0, w0, dh, dw;
    b = wb >> 9;                 // / 512
    int rem = wb & 511;
    if (axis == 0) {
        int s = rem >> 6;        // stripe index (rows)
        int w = rem & 63;
        h0 = s * SS; w0 = w; dh = 1; dw = 0;
    } else {
        int h = rem >> 3;
        int s = rem & 7;         // stripe index (cols)
        h0 = h; w0 = s * SS; dh = 0; dw = 1;
    }
    const int cbase = axis * HALF;            // channel offset within q/k/v
    const float* lw = axis ? lepe_v : lepe_h; // (3,3,1,256) row-major

    // Stage q,k,v: 8 positions x 256 channels (the active half)
    #pragma unroll
    for (int i = 0; i < SS; ++i) {
        int l = (h0 + dh * i) * Wc + (w0 + dw * i);
        size_t base = ((size_t)(b * Lc + l)) * QKVN + cbase;
        qs[i * SROW + tid] = qkv[base + tid];
        ks[i * SROW + tid] = qkv[base + Cc + tid];
        vs[i * SROW + tid] = qkv[base + 2 * Cc + tid];
    }
    __syncthreads();

    const float inv_scale = 0.17677669529663687f;   // 1/sqrt(32)
    const int ch = warp * HD;                        // head channel base (in half)

    // S = q k^T / scale ; each lane does 2 of the 64 (i,j) pairs
    #pragma unroll
    for (int p = lane; p < 64; p += 32) {
        int i = p >> 3, j = p & 7;
        float acc = 0.f;
        #pragma unroll
        for (int d = 0; d < HD; ++d)
            acc += qs[i * SROW + ch + d] * ks[j * SROW + ch + d];
        Ssm[warp][p] = acc * inv_scale;
    }
    __syncwarp();

    // softmax per row (lanes 0..7 each own a row)
    if (lane < 8) {
        int i = lane;
        float m = -INFINITY;
        #pragma unroll
        for (int j = 0; j < 8; ++j) m = fmaxf(m, Ssm[warp][i * 8 + j]);
        float e[8], sum = 0.f;
        #pragma unroll
        for (int j = 0; j < 8; ++j) { e[j] = __expf(Ssm[warp][i * 8 + j] - m); sum += e[j]; }
        float inv = 1.0f / sum;
        #pragma unroll
        for (int j = 0; j < 8; ++j) Ssm[warp][i * 8 + j] = e[j] * inv;
    }
    __syncwarp();

    // out = P @ V + LePE(v); lane = hd dim
    const int d = lane;
    float wl[9];
    #pragma unroll
    for (int t = 0; t < 9; ++t) wl[t] = lw[t * HALF + ch + d];

    #pragma unroll
    for (int i = 0; i < SS; ++i) {
        float acc = 0.f;
        #pragma unroll
        for (int j = 0; j < 8; ++j)
            acc += Ssm[warp][i * 8 + j] * vs[j * SROW + ch + d];

        int hh = h0 + dh * i, ww = w0 + dw * i;
        float lep = 0.f;
        #pragma unroll
        for (int kh = 0; kh < 3; ++kh) {
            int h2 = hh + kh - 1;
            if (h2 < 0 || h2 >= Hc) continue;
            #pragma unroll
            for (int kw = 0; kw < 3; ++kw) {
                int w2 = ww + kw - 1;
                if (w2 < 0 || w2 >= Wc) continue;
                size_t vb = ((size_t)(b * Lc + h2 * Wc + w2)) * QKVN
                          + 2 * Cc + cbase + ch + d;
                lep = fmaf(qkv[vb], wl[kh * 3 + kw], lep);
            }
        }
        int l = hh * Wc + ww;
        out[((size_t)(b * Lc + l)) * Cc + cbase + ch + d] = acc + lep;
    }
}

// ----------------------------------------------------------------------------
// Launch
// Inputs (metadata order): x, w_qkv, w_proj, b_proj, lepe_h_w, lepe_v_w, H, W
// ----------------------------------------------------------------------------
extern "C" void kernel_launch(void* const* d_in, const int* in_sizes, int n_in,
                              void* d_out, int out_size)
{
    const float* x       = (const float*)d_in[0];
    const float* w_qkv   = (const float*)d_in[1];
    const float* w_proj  = (const float*)d_in[2];
    const float* b_proj  = (const float*)d_in[3];
    const float* lepe_h  = (const float*)d_in[4];
    const float* lepe_v  = (const float*)d_in[5];
    float* out = (float*)d_out;

    void* p_qkv = nullptr;
    void* p_attn = nullptr;
    cudaGetSymbolAddress(&p_qkv, g_qkv);
    cudaGetSymbolAddress(&p_attn, g_attn);
    float* qkv  = (float*)p_qkv;
    float* attn = (float*)p_attn;

    // 1) qkv = x @ w_qkv^T : (32768,512) x (1536,512)^T
    {
        dim3 grid(QKVN / BN, Mrows / BM);
        sgemm_nt<<<grid, 256>>>(x, w_qkv, nullptr, qkv, Mrows, QKVN, Cc);
    }

    // 2) stripe attention (both halves) + LePE
    stripe_attn_kernel<<<8192, 256>>>(qkv, lepe_h, lepe_v, attn);

    // 3) out = attn @ w_proj^T + b_proj : (32768,512) x (512,512)^T
    {
        dim3 grid(Cc / BN, Mrows / BM);
        sgemm_nt<<<grid, 256>>>(attn, w_proj, b_proj, out, Mrows, Cc, Cc);
    }
}

// round 5
// speedup vs baseline: 2.6575x; 2.6575x over previous
#include <cuda_runtime.h>
#include <cuda_bf16.h>
#include <math.h>
#include <cstdint>

// ----------------------------------------------------------------------------
// CSwinAttention — R5 (= R3/R4 resubmit after two broker failures):
// tf32 mma.sync GEMMs (harness PTX targets sm_100 without 'a' -> no tcgen05)
// + fused stripe attention/LePE.
// ----------------------------------------------------------------------------

#define Hc     64
#define Wc     64
#define Lc     4096
#define Cc     512
#define Mrows  32768
#define QKVN   1536
#define HALF   256
#define SS     8
#define HD     32
#define KK     512

// Scratch (allocation-free rule: __device__ globals)
__device__ float g_qkv[(size_t)Mrows * QKVN];   // ~201 MB
__device__ float g_attn[(size_t)Mrows * Cc];    // ~67 MB

// ----------------------------------------------------------------------------
// tf32 GEMM NT: C[M,N] = A[M,512] * B[N,512]^T (+bias)
// 128x128 CTA tile, 256 threads (8 warps = 4M x 2N), warp tile 32x64.
// mma.sync m16n8k8 tf32, BK=16, 3-stage cp.async pipeline.
// smem per stage: A[128][20] + B[128][20] floats (pad 4 -> conflict-free).
// ----------------------------------------------------------------------------
#define BM 128
#define BN 128
#define BK 16
#define NSTAGE 3
#define NT (KK / BK)          // 32 k-tiles
#define RSTR 20               // row stride in floats (16 + 4 pad)
#define STG_FLTS (128 * RSTR) // 2560 floats per matrix per stage
#define GEMM_SMEM_BYTES (NSTAGE * 2 * STG_FLTS * 4)   // 61440

__device__ __forceinline__ void cp16(uint32_t saddr, const void* gaddr) {
    asm volatile("cp.async.cg.shared.global [%0], [%1], 16;"
                 :: "r"(saddr), "l"(gaddr));
}
#define CP_COMMIT() asm volatile("cp.async.commit_group;" ::: "memory")
#define CP_WAIT(n)  asm volatile("cp.async.wait_group %0;" :: "n"(n) : "memory")

__device__ __forceinline__ uint32_t smem_u32(const void* p) {
    uint32_t a;
    asm("{ .reg .u64 t; cvta.to.shared.u64 t, %1; cvt.u32.u64 %0, t; }"
        : "=r"(a) : "l"(p));
    return a;
}

__device__ __forceinline__ uint32_t f2tf32(float f) {
    uint32_t u;
    asm("cvt.rna.tf32.f32 %0, %1;" : "=r"(u) : "f"(f));
    return u;
}

__device__ __forceinline__ void mma_tf32(
    float& c0, float& c1, float& c2, float& c3,
    uint32_t a0, uint32_t a1, uint32_t a2, uint32_t a3,
    uint32_t b0, uint32_t b1)
{
    asm volatile(
        "mma.sync.aligned.m16n8k8.row.col.f32.tf32.tf32.f32 "
        "{%0,%1,%2,%3}, {%4,%5,%6,%7}, {%8,%9}, {%0,%1,%2,%3};"
        : "+f"(c0), "+f"(c1), "+f"(c2), "+f"(c3)
        : "r"(a0), "r"(a1), "r"(a2), "r"(a3), "r"(b0), "r"(b1));
}

__global__ __launch_bounds__(256, 2)
void gemm_tf32(const float* __restrict__ A, const float* __restrict__ Bw,
               const float* __restrict__ bias, float* __restrict__ C, int N)
{
    extern __shared__ __align__(16) float smem[];
    // layout: [stage][0:A(2560f) | 2560:B(2560f)]
    const int tid  = threadIdx.x;
    const int w    = tid >> 5;
    const int lane = tid & 31;
    const int row0 = blockIdx.y * BM;
    const int col0 = blockIdx.x * BN;
    const int warpM = (w & 3) * 32;
    const int warpN = (w >> 2) * 64;

    const uint32_t sb = smem_u32(smem);
    const int chunk = tid & 3;      // 16B chunk within 16-float row
    const int lrow  = tid >> 2;     // 0..63; rows lrow and lrow+64

    const float* Arow0 = A  + (size_t)(row0 + lrow) * KK + chunk * 4;
    const float* Arow1 = A  + (size_t)(row0 + lrow + 64) * KK + chunk * 4;
    const float* Brow0 = Bw + (size_t)(col0 + lrow) * KK + chunk * 4;
    const float* Brow1 = Bw + (size_t)(col0 + lrow + 64) * KK + chunk * 4;
    const uint32_t soA0 = (uint32_t)(lrow * RSTR + chunk * 4) * 4u;
    const uint32_t soA1 = (uint32_t)((lrow + 64) * RSTR + chunk * 4) * 4u;

    float acc[2][8][4];
    #pragma unroll
    for (int mt = 0; mt < 2; ++mt)
        #pragma unroll
        for (int nt = 0; nt < 8; ++nt)
            #pragma unroll
            for (int i = 0; i < 4; ++i) acc[mt][nt][i] = 0.f;

    // prologue: tiles 0..NSTAGE-2
    #pragma unroll
    for (int p = 0; p < NSTAGE - 1; ++p) {
        const uint32_t st = sb + (uint32_t)p * (2 * STG_FLTS * 4);
        const int koff = p * BK;
        cp16(st + soA0, Arow0 + koff);
        cp16(st + soA1, Arow1 + koff);
        cp16(st + STG_FLTS * 4 + soA0, Brow0 + koff);
        cp16(st + STG_FLTS * 4 + soA1, Brow1 + koff);
        CP_COMMIT();
    }

    const int qrow = lane >> 2;   // 0..7
    const int qcol = lane & 3;    // 0..3

    for (int kt = 0; kt < NT; ++kt) {
        if (kt < NT - 1) { CP_WAIT(NSTAGE - 2); } else { CP_WAIT(0); }
        __syncthreads();

        // issue loads for tile kt+NSTAGE-1 into stage just freed
        if (kt + NSTAGE - 1 < NT) {
            const int s = (kt + NSTAGE - 1) % NSTAGE;
            const uint32_t st = sb + (uint32_t)s * (2 * STG_FLTS * 4);
            const int koff = (kt + NSTAGE - 1) * BK;
            cp16(st + soA0, Arow0 + koff);
            cp16(st + soA1, Arow1 + koff);
            cp16(st + STG_FLTS * 4 + soA0, Brow0 + koff);
            cp16(st + STG_FLTS * 4 + soA1, Brow1 + koff);
            CP_COMMIT();
        }

        const float* As = smem + (size_t)(kt % NSTAGE) * (2 * STG_FLTS);
        const float* Bs = As + STG_FLTS;

        #pragma unroll
        for (int ks = 0; ks < 2; ++ks) {
            const int k0 = ks * 8;
            uint32_t af[2][4], bf[8][2];
            #pragma unroll
            for (int mt = 0; mt < 2; ++mt) {
                const int ar = warpM + mt * 16 + qrow;
                af[mt][0] = f2tf32(As[ar * RSTR + k0 + qcol]);
                af[mt][1] = f2tf32(As[(ar + 8) * RSTR + k0 + qcol]);
                af[mt][2] = f2tf32(As[ar * RSTR + k0 + qcol + 4]);
                af[mt][3] = f2tf32(As[(ar + 8) * RSTR + k0 + qcol + 4]);
            }
            #pragma unroll
            for (int nt = 0; nt < 8; ++nt) {
                const int br = warpN + nt * 8 + qrow;
                bf[nt][0] = f2tf32(Bs[br * RSTR + k0 + qcol]);
                bf[nt][1] = f2tf32(Bs[br * RSTR + k0 + qcol + 4]);
            }
            #pragma unroll
            for (int mt = 0; mt < 2; ++mt)
                #pragma unroll
                for (int nt = 0; nt < 8; ++nt)
                    mma_tf32(acc[mt][nt][0], acc[mt][nt][1],
                             acc[mt][nt][2], acc[mt][nt][3],
                             af[mt][0], af[mt][1], af[mt][2], af[mt][3],
                             bf[nt][0], bf[nt][1]);
        }
    }

    // epilogue
    #pragma unroll
    for (int mt = 0; mt < 2; ++mt) {
        const int r0 = row0 + warpM + mt * 16 + qrow;
        #pragma unroll
        for (int nt = 0; nt < 8; ++nt) {
            const int c = col0 + warpN + nt * 8 + qcol * 2;
            float2 v0 = make_float2(acc[mt][nt][0], acc[mt][nt][1]);
            float2 v1 = make_float2(acc[mt][nt][2], acc[mt][nt][3]);
            if (bias) {
                const float b0 = bias[c], b1 = bias[c + 1];
                v0.x += b0; v0.y += b1;
                v1.x += b0; v1.y += b1;
            }
            *reinterpret_cast<float2*>(C + (size_t)r0 * N + c) = v0;
            *reinterpret_cast<float2*>(C + (size_t)(r0 + 8) * N + c) = v1;
        }
    }
}

// ----------------------------------------------------------------------------
// Stripe attention + LePE
// ----------------------------------------------------------------------------
#define SROW 264

__global__ __launch_bounds__(256) void stripe_attn_kernel(
    const float* __restrict__ qkv,
    const float* __restrict__ lepe_h,
    const float* __restrict__ lepe_v,
    float* __restrict__ out)
{
    __shared__ float qs[SS * SROW];
    __shared__ float ks[SS * SROW];
    __shared__ float vs[SS * SROW];
    __shared__ float Ssm[8][64];

    const int blk  = blockIdx.x;
    const int axis = (blk >= 4096) ? 1 : 0;
    const int wb   = blk & 4095;
    const int tid  = threadIdx.x;
    const int warp = tid >> 5;
    const int lane = tid & 31;

    int b = wb >> 9;
    int rem = wb & 511;
    int h0, w0, dh, dw;
    if (axis == 0) {
        int s = rem >> 6;
        int ww = rem & 63;
        h0 = s * SS; w0 = ww; dh = 1; dw = 0;
    } else {
        int hh = rem >> 3;
        int s = rem & 7;
        h0 = hh; w0 = s * SS; dh = 0; dw = 1;
    }
    const int cbase = axis * HALF;
    const float* lw = axis ? lepe_v : lepe_h;

    #pragma unroll
    for (int i = 0; i < SS; ++i) {
        int l = (h0 + dh * i) * Wc + (w0 + dw * i);
        size_t base = ((size_t)(b * Lc + l)) * QKVN + cbase;
        qs[i * SROW + tid] = qkv[base + tid];
        ks[i * SROW + tid] = qkv[base + Cc + tid];
        vs[i * SROW + tid] = qkv[base + 2 * Cc + tid];
    }
    __syncthreads();

    const float inv_scale = 0.17677669529663687f;
    const int ch = warp * HD;

    #pragma unroll
    for (int p = lane; p < 64; p += 32) {
        int i = p >> 3, j = p & 7;
        float acc = 0.f;
        #pragma unroll
        for (int d = 0; d < HD; ++d)
            acc += qs[i * SROW + ch + d] * ks[j * SROW + ch + d];
        Ssm[warp][p] = acc * inv_scale;
    }
    __syncwarp();

    if (lane < 8) {
        int i = lane;
        float m = -INFINITY;
        #pragma unroll
        for (int j = 0; j < 8; ++j) m = fmaxf(m, Ssm[warp][i * 8 + j]);
        float e[8], sum = 0.f;
        #pragma unroll
        for (int j = 0; j < 8; ++j) { e[j] = __expf(Ssm[warp][i * 8 + j] - m); sum += e[j]; }
        float inv = 1.0f / sum;
        #pragma unroll
        for (int j = 0; j < 8; ++j) Ssm[warp][i * 8 + j] = e[j] * inv;
    }
    __syncwarp();

    const int d = lane;
    float wl[9];
    #pragma unroll
    for (int t = 0; t < 9; ++t) wl[t] = lw[t * HALF + ch + d];

    #pragma unroll
    for (int i = 0; i < SS; ++i) {
        float acc = 0.f;
        #pragma unroll
        for (int j = 0; j < 8; ++j)
            acc += Ssm[warp][i * 8 + j] * vs[j * SROW + ch + d];

        int hh = h0 + dh * i, ww = w0 + dw * i;
        float lep = 0.f;
        #pragma unroll
        for (int kh = 0; kh < 3; ++kh) {
            int h2 = hh + kh - 1;
            if (h2 < 0 || h2 >= Hc) continue;
            #pragma unroll
            for (int kw = 0; kw < 3; ++kw) {
                int w2 = ww + kw - 1;
                if (w2 < 0 || w2 >= Wc) continue;
                size_t vb = ((size_t)(b * Lc + h2 * Wc + w2)) * QKVN
                          + 2 * Cc + cbase + ch + d;
                lep = fmaf(qkv[vb], wl[kh * 3 + kw], lep);
            }
        }
        int l = hh * Wc + ww;
        out[((size_t)(b * Lc + l)) * Cc + cbase + ch + d] = acc + lep;
    }
}

// ----------------------------------------------------------------------------
// Launch.  Inputs: x, w_qkv, w_proj, b_proj, lepe_h_w, lepe_v_w, H, W
// ----------------------------------------------------------------------------
extern "C" void kernel_launch(void* const* d_in, const int* in_sizes, int n_in,
                              void* d_out, int out_size)
{
    const float* x       = (const float*)d_in[0];
    const float* w_qkv   = (const float*)d_in[1];
    const float* w_proj  = (const float*)d_in[2];
    const float* b_proj  = (const float*)d_in[3];
    const float* lepe_h  = (const float*)d_in[4];
    const float* lepe_v  = (const float*)d_in[5];
    float* out = (float*)d_out;

    void* p_qkv = nullptr;
    void* p_attn = nullptr;
    cudaGetSymbolAddress(&p_qkv, g_qkv);
    cudaGetSymbolAddress(&p_attn, g_attn);
    float* qkv  = (float*)p_qkv;
    float* attn = (float*)p_attn;

    cudaFuncSetAttribute(gemm_tf32,
                         cudaFuncAttributeMaxDynamicSharedMemorySize,
                         GEMM_SMEM_BYTES);

    // 1) qkv = x @ w_qkv^T : (32768,512) x (1536,512)^T
    {
        dim3 grid(QKVN / BN, Mrows / BM);
        gemm_tf32<<<grid, 256, GEMM_SMEM_BYTES>>>(x, w_qkv, nullptr, qkv, QKVN);
    }

    // 2) stripe attention (both halves) + LePE
    stripe_attn_kernel<<<8192, 256>>>(qkv, lepe_h, lepe_v, attn);

    // 3) out = attn @ w_proj^T + b_proj : (32768,512) x (512,512)^T
    {
        dim3 grid(Cc / BN, Mrows / BM);
        gemm_tf32<<<grid, 256, GEMM_SMEM_BYTES>>>(attn, w_proj, b_proj, out, Cc);
    }
}

// round 6
// speedup vs baseline: 2.9771x; 1.1203x over previous
#include <cuda_runtime.h>
#include <cuda_bf16.h>
#include <math.h>
#include <cstdint>

// ----------------------------------------------------------------------------
// CSwinAttention — R6: tf32 mma.sync GEMMs with ldmatrix fragment loads and
// pre-rounded tf32 operands (no cvt in mainloop) + fused stripe attn/LePE.
// ----------------------------------------------------------------------------

#define Hc     64
#define Wc     64
#define Lc     4096
#define Cc     512
#define Mrows  32768
#define QKVN   1536
#define HALF   256
#define SS     8
#define HD     32
#define KK     512

// Scratch (allocation-free rule: __device__ globals)
__device__ float g_qkv[(size_t)Mrows * QKVN];    // ~201 MB (fp32 qkv)
__device__ float g_attn[(size_t)Mrows * Cc];     // ~67 MB (tf32-rounded attn)
__device__ float g_xr[(size_t)Mrows * Cc];       // ~67 MB (tf32-rounded x)
__device__ float g_wqkvr[(size_t)QKVN * Cc];     // 3 MB  (tf32-rounded w_qkv)
__device__ float g_wpr[(size_t)Cc * Cc];         // 1 MB  (tf32-rounded w_proj)

// ----------------------------------------------------------------------------
// helpers
// ----------------------------------------------------------------------------
__device__ __forceinline__ void cp16(uint32_t saddr, const void* gaddr) {
    asm volatile("cp.async.cg.shared.global [%0], [%1], 16;"
                 :: "r"(saddr), "l"(gaddr));
}
#define CP_COMMIT() asm volatile("cp.async.commit_group;" ::: "memory")
#define CP_WAIT(n)  asm volatile("cp.async.wait_group %0;" :: "n"(n) : "memory")

__device__ __forceinline__ uint32_t smem_u32(const void* p) {
    uint32_t a;
    asm("{ .reg .u64 t; cvta.to.shared.u64 t, %1; cvt.u32.u64 %0, t; }"
        : "=r"(a) : "l"(p));
    return a;
}

__device__ __forceinline__ uint32_t f2tf32(float f) {
    uint32_t u;
    asm("cvt.rna.tf32.f32 %0, %1;" : "=r"(u) : "f"(f));
    return u;
}

__device__ __forceinline__ void mma_tf32(
    float& c0, float& c1, float& c2, float& c3,
    uint32_t a0, uint32_t a1, uint32_t a2, uint32_t a3,
    uint32_t b0, uint32_t b1)
{
    asm volatile(
        "mma.sync.aligned.m16n8k8.row.col.f32.tf32.tf32.f32 "
        "{%0,%1,%2,%3}, {%4,%5,%6,%7}, {%8,%9}, {%0,%1,%2,%3};"
        : "+f"(c0), "+f"(c1), "+f"(c2), "+f"(c3)
        : "r"(a0), "r"(a1), "r"(a2), "r"(a3), "r"(b0), "r"(b1));
}

#define LDSM_X4(r, addr) \
    asm volatile("ldmatrix.sync.aligned.m8n8.x4.shared.b16 {%0,%1,%2,%3}, [%4];" \
        : "=r"((r)[0]), "=r"((r)[1]), "=r"((r)[2]), "=r"((r)[3]) : "r"(addr))

// ----------------------------------------------------------------------------
// prepass: round fp32 -> tf32 (low 13 mantissa bits cleared, RNA)
// ----------------------------------------------------------------------------
__global__ void round_tf32_kernel(const float* __restrict__ in,
                                  float* __restrict__ out, int n4)
{
    int i = blockIdx.x * blockDim.x + threadIdx.x;
    if (i < n4) {
        float4 v = reinterpret_cast<const float4*>(in)[i];
        float4 r;
        r.x = __uint_as_float(f2tf32(v.x));
        r.y = __uint_as_float(f2tf32(v.y));
        r.z = __uint_as_float(f2tf32(v.z));
        r.w = __uint_as_float(f2tf32(v.w));
        reinterpret_cast<float4*>(out)[i] = r;
    }
}

// ----------------------------------------------------------------------------
// tf32 GEMM NT: C[M,N] = A[M,512] * B[N,512]^T (+bias); A,B pre-rounded tf32.
// 128x128 CTA tile, 256 threads (8 warps = 4M x 2N), warp tile 32x64.
// BK=16, 3-stage cp.async pipeline, ldmatrix.x4 fragment loads.
// ----------------------------------------------------------------------------
#define BM 128
#define BN 128
#define BK 16
#define NSTAGE 3
#define NT (KK / BK)          // 32 k-tiles
#define RSTR 20               // row stride in floats (16 + 4 pad)
#define STG_FLTS (128 * RSTR) // 2560 floats per matrix per stage
#define STG_BYTES (2 * STG_FLTS * 4)
#define GEMM_SMEM_BYTES (NSTAGE * STG_BYTES)   // 61440

__global__ __launch_bounds__(256, 2)
void gemm_tf32(const float* __restrict__ A, const float* __restrict__ Bw,
               const float* __restrict__ bias, float* __restrict__ C, int N)
{
    extern __shared__ __align__(16) float smem[];
    const int tid  = threadIdx.x;
    const int w    = tid >> 5;
    const int lane = tid & 31;
    const int row0 = blockIdx.y * BM;
    const int col0 = blockIdx.x * BN;
    const int warpM = (w & 3) * 32;
    const int warpN = (w >> 2) * 64;

    const uint32_t sb = smem_u32(smem);
    const int chunk = tid & 3;      // 16B chunk within 16-float row
    const int lrow  = tid >> 2;     // 0..63; rows lrow and lrow+64

    const float* Arow0 = A  + (size_t)(row0 + lrow) * KK + chunk * 4;
    const float* Arow1 = A  + (size_t)(row0 + lrow + 64) * KK + chunk * 4;
    const float* Brow0 = Bw + (size_t)(col0 + lrow) * KK + chunk * 4;
    const float* Brow1 = Bw + (size_t)(col0 + lrow + 64) * KK + chunk * 4;
    const uint32_t soA0 = (uint32_t)(lrow * RSTR + chunk * 4) * 4u;
    const uint32_t soA1 = (uint32_t)((lrow + 64) * RSTR + chunk * 4) * 4u;

    // ldmatrix per-lane source offsets (within a stage's A / B block).
    // matrix index m = lane/8, row-in-matrix i = lane%8.
    const int lm = lane >> 3;
    const int li = lane & 7;
    // A, tile mt: m0=(rows+0..7,k 0..3) m1=(rows+8..15,k 0..3)
    //             m2=(rows+0..7,k 4..7) m3=(rows+8..15,k 4..7)
    uint32_t aoff[2], boff[4];
    #pragma unroll
    for (int mt = 0; mt < 2; ++mt) {
        const int r = warpM + mt * 16 + (lm & 1) * 8 + li;
        aoff[mt] = (uint32_t)(r * RSTR + (lm >> 1) * 4) * 4u;
    }
    // B, pair p covers nt=2p,2p+1: m0=(nt0,k 0..3) m1=(nt0,k 4..7)
    //                              m2=(nt1,k 0..3) m3=(nt1,k 4..7)
    #pragma unroll
    for (int p = 0; p < 4; ++p) {
        const int r = warpN + (p * 2 + (lm >> 1)) * 8 + li;
        boff[p] = (uint32_t)(r * RSTR + (lm & 1) * 4) * 4u + (uint32_t)STG_FLTS * 4u;
    }

    float acc[2][8][4];
    #pragma unroll
    for (int mt = 0; mt < 2; ++mt)
        #pragma unroll
        for (int nt = 0; nt < 8; ++nt)
            #pragma unroll
            for (int i = 0; i < 4; ++i) acc[mt][nt][i] = 0.f;

    // prologue: tiles 0..NSTAGE-2
    #pragma unroll
    for (int p = 0; p < NSTAGE - 1; ++p) {
        const uint32_t st = sb + (uint32_t)p * STG_BYTES;
        const int koff = p * BK;
        cp16(st + soA0, Arow0 + koff);
        cp16(st + soA1, Arow1 + koff);
        cp16(st + STG_FLTS * 4 + soA0, Brow0 + koff);
        cp16(st + STG_FLTS * 4 + soA1, Brow1 + koff);
        CP_COMMIT();
    }

    const int qrow = lane >> 2;
    const int qcol = lane & 3;

    for (int kt = 0; kt < NT; ++kt) {
        if (kt < NT - 1) { CP_WAIT(NSTAGE - 2); } else { CP_WAIT(0); }
        __syncthreads();

        if (kt + NSTAGE - 1 < NT) {
            const int s = (kt + NSTAGE - 1) % NSTAGE;
            const uint32_t st = sb + (uint32_t)s * STG_BYTES;
            const int koff = (kt + NSTAGE - 1) * BK;
            cp16(st + soA0, Arow0 + koff);
            cp16(st + soA1, Arow1 + koff);
            cp16(st + STG_FLTS * 4 + soA0, Brow0 + koff);
            cp16(st + STG_FLTS * 4 + soA1, Brow1 + koff);
            CP_COMMIT();
        }

        const uint32_t stg = sb + (uint32_t)(kt % NSTAGE) * STG_BYTES;

        #pragma unroll
        for (int ks = 0; ks < 2; ++ks) {
            const uint32_t kb = (uint32_t)(ks * 8 * 4);   // k0 in bytes
            uint32_t af[2][4], bf[4][4];
            #pragma unroll
            for (int mt = 0; mt < 2; ++mt)
                LDSM_X4(af[mt], stg + aoff[mt] + kb);
            #pragma unroll
            for (int p = 0; p < 4; ++p)
                LDSM_X4(bf[p], stg + boff[p] + kb);

            #pragma unroll
            for (int mt = 0; mt < 2; ++mt)
                #pragma unroll
                for (int nt = 0; nt < 8; ++nt) {
                    const int p = nt >> 1;
                    const int o = (nt & 1) * 2;
                    mma_tf32(acc[mt][nt][0], acc[mt][nt][1],
                             acc[mt][nt][2], acc[mt][nt][3],
                             af[mt][0], af[mt][1], af[mt][2], af[mt][3],
                             bf[p][o], bf[p][o + 1]);
                }
        }
    }

    // epilogue
    #pragma unroll
    for (int mt = 0; mt < 2; ++mt) {
        const int r0 = row0 + warpM + mt * 16 + qrow;
        #pragma unroll
        for (int nt = 0; nt < 8; ++nt) {
            const int c = col0 + warpN + nt * 8 + qcol * 2;
            float2 v0 = make_float2(acc[mt][nt][0], acc[mt][nt][1]);
            float2 v1 = make_float2(acc[mt][nt][2], acc[mt][nt][3]);
            if (bias) {
                const float b0 = bias[c], b1 = bias[c + 1];
                v0.x += b0; v0.y += b1;
                v1.x += b0; v1.y += b1;
            }
            *reinterpret_cast<float2*>(C + (size_t)r0 * N + c) = v0;
            *reinterpret_cast<float2*>(C + (size_t)(r0 + 8) * N + c) = v1;
        }
    }
}

// ----------------------------------------------------------------------------
// Stripe attention + LePE. Output rounded to tf32 (feeds proj GEMM directly).
// ----------------------------------------------------------------------------
#define SROW 264

__global__ __launch_bounds__(256) void stripe_attn_kernel(
    const float* __restrict__ qkv,
    const float* __restrict__ lepe_h,
    const float* __restrict__ lepe_v,
    float* __restrict__ out)
{
    __shared__ float qs[SS * SROW];
    __shared__ float ks[SS * SROW];
    __shared__ float vs[SS * SROW];
    __shared__ float Ssm[8][64];

    const int blk  = blockIdx.x;
    const int axis = (blk >= 4096) ? 1 : 0;
    const int wb   = blk & 4095;
    const int tid  = threadIdx.x;
    const int warp = tid >> 5;
    const int lane = tid & 31;

    int b = wb >> 9;
    int rem = wb & 511;
    int h0, w0, dh, dw;
    if (axis == 0) {
        int s = rem >> 6;
        int ww = rem & 63;
        h0 = s * SS; w0 = ww; dh = 1; dw = 0;
    } else {
        int hh = rem >> 3;
        int s = rem & 7;
        h0 = hh; w0 = s * SS; dh = 0; dw = 1;
    }
    const int cbase = axis * HALF;
    const float* lw = axis ? lepe_v : lepe_h;

    #pragma unroll
    for (int i = 0; i < SS; ++i) {
        int l = (h0 + dh * i) * Wc + (w0 + dw * i);
        size_t base = ((size_t)(b * Lc + l)) * QKVN + cbase;
        qs[i * SROW + tid] = qkv[base + tid];
        ks[i * SROW + tid] = qkv[base + Cc + tid];
        vs[i * SROW + tid] = qkv[base + 2 * Cc + tid];
    }
    __syncthreads();

    const float inv_scale = 0.17677669529663687f;
    const int ch = warp * HD;

    #pragma unroll
    for (int p = lane; p < 64; p += 32) {
        int i = p >> 3, j = p & 7;
        float acc = 0.f;
        #pragma unroll
        for (int d = 0; d < HD; ++d)
            acc += qs[i * SROW + ch + d] * ks[j * SROW + ch + d];
        Ssm[warp][p] = acc * inv_scale;
    }
    __syncwarp();

    if (lane < 8) {
        int i = lane;
        float m = -INFINITY;
        #pragma unroll
        for (int j = 0; j < 8; ++j) m = fmaxf(m, Ssm[warp][i * 8 + j]);
        float e[8], sum = 0.f;
        #pragma unroll
        for (int j = 0; j < 8; ++j) { e[j] = __expf(Ssm[warp][i * 8 + j] - m); sum += e[j]; }
        float inv = 1.0f / sum;
        #pragma unroll
        for (int j = 0; j < 8; ++j) Ssm[warp][i * 8 + j] = e[j] * inv;
    }
    __syncwarp();

    const int d = lane;
    float wl[9];
    #pragma unroll
    for (int t = 0; t < 9; ++t) wl[t] = lw[t * HALF + ch + d];

    #pragma unroll
    for (int i = 0; i < SS; ++i) {
        float acc = 0.f;
        #pragma unroll
        for (int j = 0; j < 8; ++j)
            acc += Ssm[warp][i * 8 + j] * vs[j * SROW + ch + d];

        int hh = h0 + dh * i, ww = w0 + dw * i;
        float lep = 0.f;
        #pragma unroll
        for (int kh = 0; kh < 3; ++kh) {
            int h2 = hh + kh - 1;
            if (h2 < 0 || h2 >= Hc) continue;
            #pragma unroll
            for (int kw = 0; kw < 3; ++kw) {
                int w2 = ww + kw - 1;
                if (w2 < 0 || w2 >= Wc) continue;
                size_t vb = ((size_t)(b * Lc + h2 * Wc + w2)) * QKVN
                          + 2 * Cc + cbase + ch + d;
                lep = fmaf(qkv[vb], wl[kh * 3 + kw], lep);
            }
        }
        int l = hh * Wc + ww;
        // round to tf32 here (identical to what proj GEMM's cvt would do)
        out[((size_t)(b * Lc + l)) * Cc + cbase + ch + d] =
            __uint_as_float(f2tf32(acc + lep));
    }
}

// ----------------------------------------------------------------------------
// Launch.  Inputs: x, w_qkv, w_proj, b_proj, lepe_h_w, lepe_v_w, H, W
// ----------------------------------------------------------------------------
extern "C" void kernel_launch(void* const* d_in, const int* in_sizes, int n_in,
                              void* d_out, int out_size)
{
    const float* x       = (const float*)d_in[0];
    const float* w_qkv   = (const float*)d_in[1];
    const float* w_proj  = (const float*)d_in[2];
    const float* b_proj  = (const float*)d_in[3];
    const float* lepe_h  = (const float*)d_in[4];
    const float* lepe_v  = (const float*)d_in[5];
    float* out = (float*)d_out;

    void *p_qkv, *p_attn, *p_xr, *p_wqkvr, *p_wpr;
    cudaGetSymbolAddress(&p_qkv,   g_qkv);
    cudaGetSymbolAddress(&p_attn,  g_attn);
    cudaGetSymbolAddress(&p_xr,    g_xr);
    cudaGetSymbolAddress(&p_wqkvr, g_wqkvr);
    cudaGetSymbolAddress(&p_wpr,   g_wpr);
    float* qkv   = (float*)p_qkv;
    float* attn  = (float*)p_attn;
    float* xr    = (float*)p_xr;
    float* wqkvr = (float*)p_wqkvr;
    float* wpr   = (float*)p_wpr;

    cudaFuncSetAttribute(gemm_tf32,
                         cudaFuncAttributeMaxDynamicSharedMemorySize,
                         GEMM_SMEM_BYTES);

    // 0) prepass: round operands to tf32
    {
        int n4 = (Mrows * Cc) / 4;
        round_tf32_kernel<<<(n4 + 255) / 256, 256>>>(x, xr, n4);
        n4 = (QKVN * Cc) / 4;
        round_tf32_kernel<<<(n4 + 255) / 256, 256>>>(w_qkv, wqkvr, n4);
        n4 = (Cc * Cc) / 4;
        round_tf32_kernel<<<(n4 + 255) / 256, 256>>>(w_proj, wpr, n4);
    }

    // 1) qkv = x @ w_qkv^T : (32768,512) x (1536,512)^T
    {
        dim3 grid(QKVN / BN, Mrows / BM);
        gemm_tf32<<<grid, 256, GEMM_SMEM_BYTES>>>(xr, wqkvr, nullptr, qkv, QKVN);
    }

    // 2) stripe attention (both halves) + LePE (output tf32-rounded)
    stripe_attn_kernel<<<8192, 256>>>(qkv, lepe_h, lepe_v, attn);

    // 3) out = attn @ w_proj^T + b_proj : (32768,512) x (512,512)^T
    {
        dim3 grid(Cc / BN, Mrows / BM);
        gemm_tf32<<<grid, 256, GEMM_SMEM_BYTES>>>(attn, wpr, b_proj, out, Cc);
    }
}

// round 7
// speedup vs baseline: 4.5687x; 1.5346x over previous
#include <cuda_runtime.h>
#include <cuda_fp16.h>
#include <math.h>
#include <cstdint>

// ----------------------------------------------------------------------------
// CSwinAttention — R7: fp16 mma.sync m16n8k16 GEMMs (fp32 accumulate; fp16 has
// the same 11-bit significand as tf32 -> identical error profile, 2x tensor
// throughput) + fused stripe attention/LePE.
// ----------------------------------------------------------------------------

#define Hc     64
#define Wc     64
#define Lc     4096
#define Cc     512
#define Mrows  32768
#define QKVN   1536
#define HALF   256
#define SS     8
#define HD     32
#define KK     512

// Scratch (allocation-free rule: __device__ globals)
__device__ float  g_qkv[(size_t)Mrows * QKVN];    // ~201 MB fp32 qkv
__device__ __half g_attnh[(size_t)Mrows * Cc];    // ~33 MB fp16 attn
__device__ __half g_xh[(size_t)Mrows * Cc];       // ~33 MB fp16 x
__device__ __half g_wqkvh[(size_t)QKVN * Cc];     // 1.5 MB fp16 w_qkv
__device__ __half g_wph[(size_t)Cc * Cc];         // 0.5 MB fp16 w_proj

// ----------------------------------------------------------------------------
// helpers
// ----------------------------------------------------------------------------
__device__ __forceinline__ void cp16(uint32_t saddr, const void* gaddr) {
    asm volatile("cp.async.cg.shared.global [%0], [%1], 16;"
                 :: "r"(saddr), "l"(gaddr));
}
#define CP_COMMIT() asm volatile("cp.async.commit_group;" ::: "memory")
#define CP_WAIT(n)  asm volatile("cp.async.wait_group %0;" :: "n"(n) : "memory")

__device__ __forceinline__ uint32_t smem_u32(const void* p) {
    uint32_t a;
    asm("{ .reg .u64 t; cvta.to.shared.u64 t, %1; cvt.u32.u64 %0, t; }"
        : "=r"(a) : "l"(p));
    return a;
}

__device__ __forceinline__ void mma_f16(
    float& c0, float& c1, float& c2, float& c3,
    uint32_t a0, uint32_t a1, uint32_t a2, uint32_t a3,
    uint32_t b0, uint32_t b1)
{
    asm volatile(
        "mma.sync.aligned.m16n8k16.row.col.f32.f16.f16.f32 "
        "{%0,%1,%2,%3}, {%4,%5,%6,%7}, {%8,%9}, {%0,%1,%2,%3};"
        : "+f"(c0), "+f"(c1), "+f"(c2), "+f"(c3)
        : "r"(a0), "r"(a1), "r"(a2), "r"(a3), "r"(b0), "r"(b1));
}

#define LDSM_X4(r, addr) \
    asm volatile("ldmatrix.sync.aligned.m8n8.x4.shared.b16 {%0,%1,%2,%3}, [%4];" \
        : "=r"((r)[0]), "=r"((r)[1]), "=r"((r)[2]), "=r"((r)[3]) : "r"(addr))

// ----------------------------------------------------------------------------
// prepass: fp32 -> fp16 (RN)
// ----------------------------------------------------------------------------
__global__ void f2h_kernel(const float* __restrict__ in,
                           __half* __restrict__ out, int n4)
{
    int i = blockIdx.x * blockDim.x + threadIdx.x;
    if (i < n4) {
        float4 v = reinterpret_cast<const float4*>(in)[i];
        __half2 h0 = __floats2half2_rn(v.x, v.y);
        __half2 h1 = __floats2half2_rn(v.z, v.w);
        uint2 r;
        r.x = *reinterpret_cast<uint32_t*>(&h0);
        r.y = *reinterpret_cast<uint32_t*>(&h1);
        reinterpret_cast<uint2*>(out)[i] = r;
    }
}

// ----------------------------------------------------------------------------
// fp16 GEMM NT: C[M,N] = A[M,512] * B[N,512]^T (+bias); A,B fp16, C fp32.
// 128x128 CTA tile, 256 threads (8 warps = 4M x 2N), warp tile 32x64.
// BK=32 halves, 4-stage cp.async pipeline, ldmatrix.x4 fragment loads.
// smem row stride 40 halves (80 B) -> ldmatrix rows cover all 8 bank groups.
// ----------------------------------------------------------------------------
#define BM 128
#define BN 128
#define BKH 32
#define NSTAGE 4
#define NTT (KK / BKH)           // 16 k-tiles
#define RSTRH 40                 // row stride in halves (32 + 8 pad)
#define STG_HALVES (128 * RSTRH) // 5120 per matrix per stage
#define STG_BYTES (2 * STG_HALVES * 2)   // 20480
#define GEMM_SMEM_BYTES (NSTAGE * STG_BYTES)  // 81920

__global__ __launch_bounds__(256, 2)
void gemm_f16(const __half* __restrict__ A, const __half* __restrict__ Bw,
              const float* __restrict__ bias, float* __restrict__ C, int N)
{
    extern __shared__ __align__(16) char smem[];
    const int tid  = threadIdx.x;
    const int w    = tid >> 5;
    const int lane = tid & 31;
    const int row0 = blockIdx.y * BM;
    const int col0 = blockIdx.x * BN;
    const int warpM = (w & 3) * 32;
    const int warpN = (w >> 2) * 64;

    const uint32_t sb = smem_u32(smem);
    const int chunk = tid & 3;      // 16B (8-half) chunk within 32-half row
    const int lrow  = tid >> 2;     // 0..63; rows lrow and lrow+64

    const __half* Arow0 = A  + (size_t)(row0 + lrow) * KK + chunk * 8;
    const __half* Arow1 = A  + (size_t)(row0 + lrow + 64) * KK + chunk * 8;
    const __half* Brow0 = Bw + (size_t)(col0 + lrow) * KK + chunk * 8;
    const __half* Brow1 = Bw + (size_t)(col0 + lrow + 64) * KK + chunk * 8;
    const uint32_t soA0 = (uint32_t)(lrow * RSTRH + chunk * 8) * 2u;
    const uint32_t soA1 = (uint32_t)((lrow + 64) * RSTRH + chunk * 8) * 2u;
    const uint32_t bofs = (uint32_t)STG_HALVES * 2u;

    // ldmatrix per-lane offsets. lm = matrix idx (lane/8), li = row (lane%8).
    const int lm = lane >> 3;
    const int li = lane & 7;
    // A tile mt (16 rows x k16): m0=(r0..7,k0..7) m1=(r8..15,k0..7)
    //                            m2=(r0..7,k8..15) m3=(r8..15,k8..15)
    uint32_t aoff[2], boff[4];
    #pragma unroll
    for (int mt = 0; mt < 2; ++mt) {
        const int r = warpM + mt * 16 + (lm & 1) * 8 + li;
        aoff[mt] = (uint32_t)(r * RSTRH) * 2u + (uint32_t)(lm >> 1) * 16u;
    }
    // B pair p covers nt=2p,2p+1 (16 n-rows x k16):
    //   m0=(n0..7,k0..7) m1=(n0..7,k8..15) m2=(n8..15,k0..7) m3=(n8..15,k8..15)
    #pragma unroll
    for (int p = 0; p < 4; ++p) {
        const int r = warpN + p * 16 + (lm >> 1) * 8 + li;
        boff[p] = (uint32_t)(r * RSTRH) * 2u + (uint32_t)(lm & 1) * 16u + bofs;
    }

    float acc[2][8][4];
    #pragma unroll
    for (int mt = 0; mt < 2; ++mt)
        #pragma unroll
        for (int nt = 0; nt < 8; ++nt)
            #pragma unroll
            for (int i = 0; i < 4; ++i) acc[mt][nt][i] = 0.f;

    // prologue: tiles 0..NSTAGE-2
    #pragma unroll
    for (int p = 0; p < NSTAGE - 1; ++p) {
        const uint32_t st = sb + (uint32_t)p * STG_BYTES;
        const int koff = p * BKH;
        cp16(st + soA0, Arow0 + koff);
        cp16(st + soA1, Arow1 + koff);
        cp16(st + bofs + soA0, Brow0 + koff);
        cp16(st + bofs + soA1, Brow1 + koff);
        CP_COMMIT();
    }

    const int qrow = lane >> 2;
    const int qcol = lane & 3;

    for (int kt = 0; kt < NTT; ++kt) {
        if (kt < NTT - 1) { CP_WAIT(NSTAGE - 2); } else { CP_WAIT(0); }
        __syncthreads();

        if (kt + NSTAGE - 1 < NTT) {
            const int s = (kt + NSTAGE - 1) % NSTAGE;
            const uint32_t st = sb + (uint32_t)s * STG_BYTES;
            const int koff = (kt + NSTAGE - 1) * BKH;
            cp16(st + soA0, Arow0 + koff);
            cp16(st + soA1, Arow1 + koff);
            cp16(st + bofs + soA0, Brow0 + koff);
            cp16(st + bofs + soA1, Brow1 + koff);
            CP_COMMIT();
        }

        const uint32_t stg = sb + (uint32_t)(kt % NSTAGE) * STG_BYTES;

        #pragma unroll
        for (int ks = 0; ks < 2; ++ks) {
            const uint32_t kb = (uint32_t)(ks * 16 * 2);  // 16 halves in bytes
            uint32_t af[2][4], bf[4][4];
            #pragma unroll
            for (int mt = 0; mt < 2; ++mt)
                LDSM_X4(af[mt], stg + aoff[mt] + kb);
            #pragma unroll
            for (int p = 0; p < 4; ++p)
                LDSM_X4(bf[p], stg + boff[p] + kb);

            #pragma unroll
            for (int mt = 0; mt < 2; ++mt)
                #pragma unroll
                for (int nt = 0; nt < 8; ++nt) {
                    const int p = nt >> 1;
                    const int o = (nt & 1) * 2;
                    mma_f16(acc[mt][nt][0], acc[mt][nt][1],
                            acc[mt][nt][2], acc[mt][nt][3],
                            af[mt][0], af[mt][1], af[mt][2], af[mt][3],
                            bf[p][o], bf[p][o + 1]);
                }
        }
    }

    // epilogue (fp32 out, optional bias)
    #pragma unroll
    for (int mt = 0; mt < 2; ++mt) {
        const int r0 = row0 + warpM + mt * 16 + qrow;
        #pragma unroll
        for (int nt = 0; nt < 8; ++nt) {
            const int c = col0 + warpN + nt * 8 + qcol * 2;
            float2 v0 = make_float2(acc[mt][nt][0], acc[mt][nt][1]);
            float2 v1 = make_float2(acc[mt][nt][2], acc[mt][nt][3]);
            if (bias) {
                const float b0 = bias[c], b1 = bias[c + 1];
                v0.x += b0; v0.y += b1;
                v1.x += b0; v1.y += b1;
            }
            *reinterpret_cast<float2*>(C + (size_t)r0 * N + c) = v0;
            *reinterpret_cast<float2*>(C + (size_t)(r0 + 8) * N + c) = v1;
        }
    }
}

// ----------------------------------------------------------------------------
// Stripe attention + LePE. Reads fp32 qkv; writes fp16 attn (feeds proj GEMM).
// ----------------------------------------------------------------------------
#define SROW 264

__global__ __launch_bounds__(256) void stripe_attn_kernel(
    const float* __restrict__ qkv,
    const float* __restrict__ lepe_h,
    const float* __restrict__ lepe_v,
    __half* __restrict__ out)
{
    __shared__ float qs[SS * SROW];
    __shared__ float ks[SS * SROW];
    __shared__ float vs[SS * SROW];
    __shared__ float Ssm[8][64];

    const int blk  = blockIdx.x;
    const int axis = (blk >= 4096) ? 1 : 0;
    const int wb   = blk & 4095;
    const int tid  = threadIdx.x;
    const int warp = tid >> 5;
    const int lane = tid & 31;

    int b = wb >> 9;
    int rem = wb & 511;
    int h0, w0, dh, dw;
    if (axis == 0) {
        int s = rem >> 6;
        int ww = rem & 63;
        h0 = s * SS; w0 = ww; dh = 1; dw = 0;
    } else {
        int hh = rem >> 3;
        int s = rem & 7;
        h0 = hh; w0 = s * SS; dh = 0; dw = 1;
    }
    const int cbase = axis * HALF;
    const float* lw = axis ? lepe_v : lepe_h;

    #pragma unroll
    for (int i = 0; i < SS; ++i) {
        int l = (h0 + dh * i) * Wc + (w0 + dw * i);
        size_t base = ((size_t)(b * Lc + l)) * QKVN + cbase;
        qs[i * SROW + tid] = qkv[base + tid];
        ks[i * SROW + tid] = qkv[base + Cc + tid];
        vs[i * SROW + tid] = qkv[base + 2 * Cc + tid];
    }
    __syncthreads();

    const float inv_scale = 0.17677669529663687f;
    const int ch = warp * HD;

    #pragma unroll
    for (int p = lane; p < 64; p += 32) {
        int i = p >> 3, j = p & 7;
        float acc = 0.f;
        #pragma unroll
        for (int d = 0; d < HD; ++d)
            acc += qs[i * SROW + ch + d] * ks[j * SROW + ch + d];
        Ssm[warp][p] = acc * inv_scale;
    }
    __syncwarp();

    if (lane < 8) {
        int i = lane;
        float m = -INFINITY;
        #pragma unroll
        for (int j = 0; j < 8; ++j) m = fmaxf(m, Ssm[warp][i * 8 + j]);
        float e[8], sum = 0.f;
        #pragma unroll
        for (int j = 0; j < 8; ++j) { e[j] = __expf(Ssm[warp][i * 8 + j] - m); sum += e[j]; }
        float inv = 1.0f / sum;
        #pragma unroll
        for (int j = 0; j < 8; ++j) Ssm[warp][i * 8 + j] = e[j] * inv;
    }
    __syncwarp();

    const int d = lane;
    float wl[9];
    #pragma unroll
    for (int t = 0; t < 9; ++t) wl[t] = lw[t * HALF + ch + d];

    #pragma unroll
    for (int i = 0; i < SS; ++i) {
        float acc = 0.f;
        #pragma unroll
        for (int j = 0; j < 8; ++j)
            acc += Ssm[warp][i * 8 + j] * vs[j * SROW + ch + d];

        int hh = h0 + dh * i, ww = w0 + dw * i;
        float lep = 0.f;
        #pragma unroll
        for (int kh = 0; kh < 3; ++kh) {
            int h2 = hh + kh - 1;
            if (h2 < 0 || h2 >= Hc) continue;
            #pragma unroll
            for (int kw = 0; kw < 3; ++kw) {
                int w2 = ww + kw - 1;
                if (w2 < 0 || w2 >= Wc) continue;
                size_t vb = ((size_t)(b * Lc + h2 * Wc + w2)) * QKVN
                          + 2 * Cc + cbase + ch + d;
                lep = fmaf(qkv[vb], wl[kh * 3 + kw], lep);
            }
        }
        int l = hh * Wc + ww;
        out[((size_t)(b * Lc + l)) * Cc + cbase + ch + d] =
            __float2half_rn(acc + lep);
    }
}

// ----------------------------------------------------------------------------
// Launch.  Inputs: x, w_qkv, w_proj, b_proj, lepe_h_w, lepe_v_w, H, W
// ----------------------------------------------------------------------------
extern "C" void kernel_launch(void* const* d_in, const int* in_sizes, int n_in,
                              void* d_out, int out_size)
{
    const float* x       = (const float*)d_in[0];
    const float* w_qkv   = (const float*)d_in[1];
    const float* w_proj  = (const float*)d_in[2];
    const float* b_proj  = (const float*)d_in[3];
    const float* lepe_h  = (const float*)d_in[4];
    const float* lepe_v  = (const float*)d_in[5];
    float* out = (float*)d_out;

    void *p_qkv, *p_attnh, *p_xh, *p_wqkvh, *p_wph;
    cudaGetSymbolAddress(&p_qkv,   g_qkv);
    cudaGetSymbolAddress(&p_attnh, g_attnh);
    cudaGetSymbolAddress(&p_xh,    g_xh);
    cudaGetSymbolAddress(&p_wqkvh, g_wqkvh);
    cudaGetSymbolAddress(&p_wph,   g_wph);
    float*  qkv   = (float*)p_qkv;
    __half* attnh = (__half*)p_attnh;
    __half* xh    = (__half*)p_xh;
    __half* wqkvh = (__half*)p_wqkvh;
    __half* wph   = (__half*)p_wph;

    cudaFuncSetAttribute(gemm_f16,
                         cudaFuncAttributeMaxDynamicSharedMemorySize,
                         GEMM_SMEM_BYTES);

    // 0) prepass: convert operands to fp16
    {
        int n4 = (Mrows * Cc) / 4;
        f2h_kernel<<<(n4 + 255) / 256, 256>>>(x, xh, n4);
        n4 = (QKVN * Cc) / 4;
        f2h_kernel<<<(n4 + 255) / 256, 256>>>(w_qkv, wqkvh, n4);
        n4 = (Cc * Cc) / 4;
        f2h_kernel<<<(n4 + 255) / 256, 256>>>(w_proj, wph, n4);
    }

    // 1) qkv = x @ w_qkv^T : (32768,512) x (1536,512)^T  (fp16 in, fp32 out)
    {
        dim3 grid(QKVN / BN, Mrows / BM);
        gemm_f16<<<grid, 256, GEMM_SMEM_BYTES>>>(xh, wqkvh, nullptr, qkv, QKVN);
    }

    // 2) stripe attention (both halves) + LePE (fp16 output)
    stripe_attn_kernel<<<8192, 256>>>(qkv, lepe_h, lepe_v, attnh);

    // 3) out = attn @ w_proj^T + b_proj : (32768,512) x (512,512)^T
    {
        dim3 grid(Cc / BN, Mrows / BM);
        gemm_f16<<<grid, 256, GEMM_SMEM_BYTES>>>(attnh, wph, b_proj, out, Cc);
    }
}

// round 8
// speedup vs baseline: 4.9675x; 1.0873x over previous
#include <cuda_runtime.h>
#include <cuda_fp16.h>
#include <math.h>
#include <cstdint>

// ----------------------------------------------------------------------------
// CSwinAttention — R8: fp16 mma.sync GEMMs, fp16 qkv intermediate (halves
// attention memory traffic), 5-stage pipeline + fused stripe attention/LePE.
// ----------------------------------------------------------------------------

#define Hc     64
#define Wc     64
#define Lc     4096
#define Cc     512
#define Mrows  32768
#define QKVN   1536
#define HALF   256
#define SS     8
#define HD     32
#define KK     512

// Scratch (allocation-free rule: __device__ globals)
__device__ __half g_qkvh[(size_t)Mrows * QKVN];   // ~100 MB fp16 qkv
__device__ __half g_attnh[(size_t)Mrows * Cc];    // ~33 MB fp16 attn
__device__ __half g_xh[(size_t)Mrows * Cc];       // ~33 MB fp16 x
__device__ __half g_wqkvh[(size_t)QKVN * Cc];     // 1.5 MB fp16 w_qkv
__device__ __half g_wph[(size_t)Cc * Cc];         // 0.5 MB fp16 w_proj

// ----------------------------------------------------------------------------
// helpers
// ----------------------------------------------------------------------------
__device__ __forceinline__ void cp16(uint32_t saddr, const void* gaddr) {
    asm volatile("cp.async.cg.shared.global [%0], [%1], 16;"
                 :: "r"(saddr), "l"(gaddr));
}
#define CP_COMMIT() asm volatile("cp.async.commit_group;" ::: "memory")
#define CP_WAIT(n)  asm volatile("cp.async.wait_group %0;" :: "n"(n) : "memory")

__device__ __forceinline__ uint32_t smem_u32(const void* p) {
    uint32_t a;
    asm("{ .reg .u64 t; cvta.to.shared.u64 t, %1; cvt.u32.u64 %0, t; }"
        : "=r"(a) : "l"(p));
    return a;
}

__device__ __forceinline__ void mma_f16(
    float& c0, float& c1, float& c2, float& c3,
    uint32_t a0, uint32_t a1, uint32_t a2, uint32_t a3,
    uint32_t b0, uint32_t b1)
{
    asm volatile(
        "mma.sync.aligned.m16n8k16.row.col.f32.f16.f16.f32 "
        "{%0,%1,%2,%3}, {%4,%5,%6,%7}, {%8,%9}, {%0,%1,%2,%3};"
        : "+f"(c0), "+f"(c1), "+f"(c2), "+f"(c3)
        : "r"(a0), "r"(a1), "r"(a2), "r"(a3), "r"(b0), "r"(b1));
}

#define LDSM_X4(r, addr) \
    asm volatile("ldmatrix.sync.aligned.m8n8.x4.shared.b16 {%0,%1,%2,%3}, [%4];" \
        : "=r"((r)[0]), "=r"((r)[1]), "=r"((r)[2]), "=r"((r)[3]) : "r"(addr))

// ----------------------------------------------------------------------------
// prepass: fp32 -> fp16 (RN)
// ----------------------------------------------------------------------------
__global__ void f2h_kernel(const float* __restrict__ in,
                           __half* __restrict__ out, int n4)
{
    int i = blockIdx.x * blockDim.x + threadIdx.x;
    if (i < n4) {
        float4 v = reinterpret_cast<const float4*>(in)[i];
        __half2 h0 = __floats2half2_rn(v.x, v.y);
        __half2 h1 = __floats2half2_rn(v.z, v.w);
        uint2 r;
        r.x = *reinterpret_cast<uint32_t*>(&h0);
        r.y = *reinterpret_cast<uint32_t*>(&h1);
        reinterpret_cast<uint2*>(out)[i] = r;
    }
}

// ----------------------------------------------------------------------------
// fp16 GEMM NT: C[M,N] = A[M,512] * B[N,512]^T (+bias); A,B fp16.
// HALF_OUT: C fp16 (no bias path used); else C fp32 (+bias).
// 128x128 CTA tile, 256 threads (8 warps = 4M x 2N), warp tile 32x64.
// BK=32 halves, 5-stage cp.async pipeline, ldmatrix.x4 fragment loads.
// ----------------------------------------------------------------------------
#define BM 128
#define BN 128
#define BKH 32
#define NSTAGE 5
#define NTT (KK / BKH)           // 16 k-tiles
#define RSTRH 40                 // row stride in halves (32 + 8 pad)
#define STG_HALVES (128 * RSTRH) // 5120 per matrix per stage
#define STG_BYTES (2 * STG_HALVES * 2)   // 20480
#define GEMM_SMEM_BYTES (NSTAGE * STG_BYTES)  // 102400

template <bool HALF_OUT>
__global__ __launch_bounds__(256, 2)
void gemm_f16(const __half* __restrict__ A, const __half* __restrict__ Bw,
              const float* __restrict__ bias, void* __restrict__ Cv, int N)
{
    extern __shared__ __align__(16) char smem[];
    const int tid  = threadIdx.x;
    const int w    = tid >> 5;
    const int lane = tid & 31;
    const int row0 = blockIdx.y * BM;
    const int col0 = blockIdx.x * BN;
    const int warpM = (w & 3) * 32;
    const int warpN = (w >> 2) * 64;

    const uint32_t sb = smem_u32(smem);
    const int chunk = tid & 3;      // 16B (8-half) chunk within 32-half row
    const int lrow  = tid >> 2;     // 0..63; rows lrow and lrow+64

    const __half* Arow0 = A  + (size_t)(row0 + lrow) * KK + chunk * 8;
    const __half* Arow1 = A  + (size_t)(row0 + lrow + 64) * KK + chunk * 8;
    const __half* Brow0 = Bw + (size_t)(col0 + lrow) * KK + chunk * 8;
    const __half* Brow1 = Bw + (size_t)(col0 + lrow + 64) * KK + chunk * 8;
    const uint32_t soA0 = (uint32_t)(lrow * RSTRH + chunk * 8) * 2u;
    const uint32_t soA1 = (uint32_t)((lrow + 64) * RSTRH + chunk * 8) * 2u;
    const uint32_t bofs = (uint32_t)STG_HALVES * 2u;

    // ldmatrix per-lane offsets. lm = matrix idx (lane/8), li = row (lane%8).
    const int lm = lane >> 3;
    const int li = lane & 7;
    uint32_t aoff[2], boff[4];
    #pragma unroll
    for (int mt = 0; mt < 2; ++mt) {
        const int r = warpM + mt * 16 + (lm & 1) * 8 + li;
        aoff[mt] = (uint32_t)(r * RSTRH) * 2u + (uint32_t)(lm >> 1) * 16u;
    }
    #pragma unroll
    for (int p = 0; p < 4; ++p) {
        const int r = warpN + p * 16 + (lm >> 1) * 8 + li;
        boff[p] = (uint32_t)(r * RSTRH) * 2u + (uint32_t)(lm & 1) * 16u + bofs;
    }

    float acc[2][8][4];
    #pragma unroll
    for (int mt = 0; mt < 2; ++mt)
        #pragma unroll
        for (int nt = 0; nt < 8; ++nt)
            #pragma unroll
            for (int i = 0; i < 4; ++i) acc[mt][nt][i] = 0.f;

    // prologue: tiles 0..NSTAGE-2
    #pragma unroll
    for (int p = 0; p < NSTAGE - 1; ++p) {
        const uint32_t st = sb + (uint32_t)p * STG_BYTES;
        const int koff = p * BKH;
        cp16(st + soA0, Arow0 + koff);
        cp16(st + soA1, Arow1 + koff);
        cp16(st + bofs + soA0, Brow0 + koff);
        cp16(st + bofs + soA1, Brow1 + koff);
        CP_COMMIT();
    }

    const int qrow = lane >> 2;
    const int qcol = lane & 3;

    for (int kt = 0; kt < NTT; ++kt) {
        if (kt < NTT - 1) { CP_WAIT(NSTAGE - 2); } else { CP_WAIT(0); }
        __syncthreads();

        if (kt + NSTAGE - 1 < NTT) {
            const int s = (kt + NSTAGE - 1) % NSTAGE;
            const uint32_t st = sb + (uint32_t)s * STG_BYTES;
            const int koff = (kt + NSTAGE - 1) * BKH;
            cp16(st + soA0, Arow0 + koff);
            cp16(st + soA1, Arow1 + koff);
            cp16(st + bofs + soA0, Brow0 + koff);
            cp16(st + bofs + soA1, Brow1 + koff);
            CP_COMMIT();
        }

        const uint32_t stg = sb + (uint32_t)(kt % NSTAGE) * STG_BYTES;

        #pragma unroll
        for (int ks = 0; ks < 2; ++ks) {
            const uint32_t kb = (uint32_t)(ks * 16 * 2);
            uint32_t af[2][4], bf[4][4];
            #pragma unroll
            for (int mt = 0; mt < 2; ++mt)
                LDSM_X4(af[mt], stg + aoff[mt] + kb);
            #pragma unroll
            for (int p = 0; p < 4; ++p)
                LDSM_X4(bf[p], stg + boff[p] + kb);

            #pragma unroll
            for (int mt = 0; mt < 2; ++mt)
                #pragma unroll
                for (int nt = 0; nt < 8; ++nt) {
                    const int p = nt >> 1;
                    const int o = (nt & 1) * 2;
                    mma_f16(acc[mt][nt][0], acc[mt][nt][1],
                            acc[mt][nt][2], acc[mt][nt][3],
                            af[mt][0], af[mt][1], af[mt][2], af[mt][3],
                            bf[p][o], bf[p][o + 1]);
                }
        }
    }

    // epilogue
    #pragma unroll
    for (int mt = 0; mt < 2; ++mt) {
        const int r0 = row0 + warpM + mt * 16 + qrow;
        #pragma unroll
        for (int nt = 0; nt < 8; ++nt) {
            const int c = col0 + warpN + nt * 8 + qcol * 2;
            if (HALF_OUT) {
                __half* C = (__half*)Cv;
                __half2 h0 = __floats2half2_rn(acc[mt][nt][0], acc[mt][nt][1]);
                __half2 h1 = __floats2half2_rn(acc[mt][nt][2], acc[mt][nt][3]);
                *reinterpret_cast<__half2*>(C + (size_t)r0 * N + c) = h0;
                *reinterpret_cast<__half2*>(C + (size_t)(r0 + 8) * N + c) = h1;
            } else {
                float* C = (float*)Cv;
                float2 v0 = make_float2(acc[mt][nt][0], acc[mt][nt][1]);
                float2 v1 = make_float2(acc[mt][nt][2], acc[mt][nt][3]);
                if (bias) {
                    const float b0 = bias[c], b1 = bias[c + 1];
                    v0.x += b0; v0.y += b1;
                    v1.x += b0; v1.y += b1;
                }
                *reinterpret_cast<float2*>(C + (size_t)r0 * N + c) = v0;
                *reinterpret_cast<float2*>(C + (size_t)(r0 + 8) * N + c) = v1;
            }
        }
    }
}

// ----------------------------------------------------------------------------
// Stripe attention + LePE. Reads fp16 qkv; fp32 math; writes fp16 attn.
// ----------------------------------------------------------------------------
#define SROW 264

__global__ __launch_bounds__(256) void stripe_attn_kernel(
    const __half* __restrict__ qkv,
    const float* __restrict__ lepe_h,
    const float* __restrict__ lepe_v,
    __half* __restrict__ out)
{
    __shared__ float qs[SS * SROW];
    __shared__ float ks[SS * SROW];
    __shared__ float vs[SS * SROW];
    __shared__ float Ssm[8][64];

    const int blk  = blockIdx.x;
    const int axis = (blk >= 4096) ? 1 : 0;
    const int wb   = blk & 4095;
    const int tid  = threadIdx.x;
    const int warp = tid >> 5;
    const int lane = tid & 31;

    int b = wb >> 9;
    int rem = wb & 511;
    int h0, w0, dh, dw;
    if (axis == 0) {
        int s = rem >> 6;
        int ww = rem & 63;
        h0 = s * SS; w0 = ww; dh = 1; dw = 0;
    } else {
        int hh = rem >> 3;
        int s = rem & 7;
        h0 = hh; w0 = s * SS; dh = 0; dw = 1;
    }
    const int cbase = axis * HALF;
    const float* lw = axis ? lepe_v : lepe_h;

    #pragma unroll
    for (int i = 0; i < SS; ++i) {
        int l = (h0 + dh * i) * Wc + (w0 + dw * i);
        size_t base = ((size_t)(b * Lc + l)) * QKVN + cbase;
        qs[i * SROW + tid] = __half2float(qkv[base + tid]);
        ks[i * SROW + tid] = __half2float(qkv[base + Cc + tid]);
        vs[i * SROW + tid] = __half2float(qkv[base + 2 * Cc + tid]);
    }
    __syncthreads();

    const float inv_scale = 0.17677669529663687f;
    const int ch = warp * HD;

    #pragma unroll
    for (int p = lane; p < 64; p += 32) {
        int i = p >> 3, j = p & 7;
        float acc = 0.f;
        #pragma unroll
        for (int d = 0; d < HD; ++d)
            acc += qs[i * SROW + ch + d] * ks[j * SROW + ch + d];
        Ssm[warp][p] = acc * inv_scale;
    }
    __syncwarp();

    if (lane < 8) {
        int i = lane;
        float m = -INFINITY;
        #pragma unroll
        for (int j = 0; j < 8; ++j) m = fmaxf(m, Ssm[warp][i * 8 + j]);
        float e[8], sum = 0.f;
        #pragma unroll
        for (int j = 0; j < 8; ++j) { e[j] = __expf(Ssm[warp][i * 8 + j] - m); sum += e[j]; }
        float inv = 1.0f / sum;
        #pragma unroll
        for (int j = 0; j < 8; ++j) Ssm[warp][i * 8 + j] = e[j] * inv;
    }
    __syncwarp();

    const int d = lane;
    float wl[9];
    #pragma unroll
    for (int t = 0; t < 9; ++t) wl[t] = lw[t * HALF + ch + d];

    #pragma unroll
    for (int i = 0; i < SS; ++i) {
        float acc = 0.f;
        #pragma unroll
        for (int j = 0; j < 8; ++j)
            acc += Ssm[warp][i * 8 + j] * vs[j * SROW + ch + d];

        int hh = h0 + dh * i, ww = w0 + dw * i;
        float lep = 0.f;
        #pragma unroll
        for (int kh = 0; kh < 3; ++kh) {
            int h2 = hh + kh - 1;
            if (h2 < 0 || h2 >= Hc) continue;
            #pragma unroll
            for (int kw = 0; kw < 3; ++kw) {
                int w2 = ww + kw - 1;
                if (w2 < 0 || w2 >= Wc) continue;
                size_t vb = ((size_t)(b * Lc + h2 * Wc + w2)) * QKVN
                          + 2 * Cc + cbase + ch + d;
                lep = fmaf(__half2float(qkv[vb]), wl[kh * 3 + kw], lep);
            }
        }
        int l = hh * Wc + ww;
        out[((size_t)(b * Lc + l)) * Cc + cbase + ch + d] =
            __float2half_rn(acc + lep);
    }
}

// ----------------------------------------------------------------------------
// Launch.  Inputs: x, w_qkv, w_proj, b_proj, lepe_h_w, lepe_v_w, H, W
// ----------------------------------------------------------------------------
extern "C" void kernel_launch(void* const* d_in, const int* in_sizes, int n_in,
                              void* d_out, int out_size)
{
    const float* x       = (const float*)d_in[0];
    const float* w_qkv   = (const float*)d_in[1];
    const float* w_proj  = (const float*)d_in[2];
    const float* b_proj  = (const float*)d_in[3];
    const float* lepe_h  = (const float*)d_in[4];
    const float* lepe_v  = (const float*)d_in[5];
    float* out = (float*)d_out;

    void *p_qkvh, *p_attnh, *p_xh, *p_wqkvh, *p_wph;
    cudaGetSymbolAddress(&p_qkvh,  g_qkvh);
    cudaGetSymbolAddress(&p_attnh, g_attnh);
    cudaGetSymbolAddress(&p_xh,    g_xh);
    cudaGetSymbolAddress(&p_wqkvh, g_wqkvh);
    cudaGetSymbolAddress(&p_wph,   g_wph);
    __half* qkvh  = (__half*)p_qkvh;
    __half* attnh = (__half*)p_attnh;
    __half* xh    = (__half*)p_xh;
    __half* wqkvh = (__half*)p_wqkvh;
    __half* wph   = (__half*)p_wph;

    cudaFuncSetAttribute(gemm_f16<true>,
                         cudaFuncAttributeMaxDynamicSharedMemorySize,
                         GEMM_SMEM_BYTES);
    cudaFuncSetAttribute(gemm_f16<false>,
                         cudaFuncAttributeMaxDynamicSharedMemorySize,
                         GEMM_SMEM_BYTES);

    // 0) prepass: convert operands to fp16
    {
        int n4 = (Mrows * Cc) / 4;
        f2h_kernel<<<(n4 + 255) / 256, 256>>>(x, xh, n4);
        n4 = (QKVN * Cc) / 4;
        f2h_kernel<<<(n4 + 255) / 256, 256>>>(w_qkv, wqkvh, n4);
        n4 = (Cc * Cc) / 4;
        f2h_kernel<<<(n4 + 255) / 256, 256>>>(w_proj, wph, n4);
    }

    // 1) qkv = x @ w_qkv^T  (fp16 in, fp16 out)
    {
        dim3 grid(QKVN / BN, Mrows / BM);
        gemm_f16<true><<<grid, 256, GEMM_SMEM_BYTES>>>(xh, wqkvh, nullptr, qkvh, QKVN);
    }

    // 2) stripe attention (both halves) + LePE (fp16 in/out)
    stripe_attn_kernel<<<8192, 256>>>(qkvh, lepe_h, lepe_v, attnh);

    // 3) out = attn @ w_proj^T + b_proj  (fp16 in, fp32 out)
    {
        dim3 grid(Cc / BN, Mrows / BM);
        gemm_f16<false><<<grid, 256, GEMM_SMEM_BYTES>>>(attnh, wph, b_proj, out, Cc);
    }
}

// round 11
// speedup vs baseline: 5.2838x; 1.0637x over previous
#include <cuda_runtime.h>
#include <cuda_fp16.h>
#include <math.h>
#include <cstdint>

// ----------------------------------------------------------------------------
// CSwinAttention — R11 (= R9/R10 resubmit; broker-failure burst): fp16
// mma.sync GEMMs + rebuilt attention memory path (uint4 q/k loads, v-halo
// smem tile serving both P@V and LePE 3x3).
// ----------------------------------------------------------------------------

#define Hc     64
#define Wc     64
#define Lc     4096
#define Cc     512
#define Mrows  32768
#define QKVN   1536
#define HALF   256
#define SS     8
#define HD     32
#define KK     512

// Scratch (allocation-free rule: __device__ globals)
__device__ __half g_qkvh[(size_t)Mrows * QKVN];   // ~100 MB fp16 qkv
__device__ __half g_attnh[(size_t)Mrows * Cc];    // ~33 MB fp16 attn
__device__ __half g_xh[(size_t)Mrows * Cc];       // ~33 MB fp16 x
__device__ __half g_wqkvh[(size_t)QKVN * Cc];     // 1.5 MB fp16 w_qkv
__device__ __half g_wph[(size_t)Cc * Cc];         // 0.5 MB fp16 w_proj

// ----------------------------------------------------------------------------
// helpers
// ----------------------------------------------------------------------------
__device__ __forceinline__ void cp16(uint32_t saddr, const void* gaddr) {
    asm volatile("cp.async.cg.shared.global [%0], [%1], 16;"
                 :: "r"(saddr), "l"(gaddr));
}
#define CP_COMMIT() asm volatile("cp.async.commit_group;" ::: "memory")
#define CP_WAIT(n)  asm volatile("cp.async.wait_group %0;" :: "n"(n) : "memory")

__device__ __forceinline__ uint32_t smem_u32(const void* p) {
    uint32_t a;
    asm("{ .reg .u64 t; cvta.to.shared.u64 t, %1; cvt.u32.u64 %0, t; }"
        : "=r"(a) : "l"(p));
    return a;
}

__device__ __forceinline__ void mma_f16(
    float& c0, float& c1, float& c2, float& c3,
    uint32_t a0, uint32_t a1, uint32_t a2, uint32_t a3,
    uint32_t b0, uint32_t b1)
{
    asm volatile(
        "mma.sync.aligned.m16n8k16.row.col.f32.f16.f16.f32 "
        "{%0,%1,%2,%3}, {%4,%5,%6,%7}, {%8,%9}, {%0,%1,%2,%3};"
        : "+f"(c0), "+f"(c1), "+f"(c2), "+f"(c3)
        : "r"(a0), "r"(a1), "r"(a2), "r"(a3), "r"(b0), "r"(b1));
}

#define LDSM_X4(r, addr) \
    asm volatile("ldmatrix.sync.aligned.m8n8.x4.shared.b16 {%0,%1,%2,%3}, [%4];" \
        : "=r"((r)[0]), "=r"((r)[1]), "=r"((r)[2]), "=r"((r)[3]) : "r"(addr))

__device__ __forceinline__ void h8_to_f8(uint4 v, float* dst) {
    const __half2* h = reinterpret_cast<const __half2*>(&v);
    float2 f0 = __half22float2(h[0]);
    float2 f1 = __half22float2(h[1]);
    float2 f2 = __half22float2(h[2]);
    float2 f3 = __half22float2(h[3]);
    float4 a = make_float4(f0.x, f0.y, f1.x, f1.y);
    float4 b = make_float4(f2.x, f2.y, f3.x, f3.y);
    *reinterpret_cast<float4*>(dst)     = a;
    *reinterpret_cast<float4*>(dst + 4) = b;
}

// ----------------------------------------------------------------------------
// prepass: fp32 -> fp16 (RN)
// ----------------------------------------------------------------------------
__global__ void f2h_kernel(const float* __restrict__ in,
                           __half* __restrict__ out, int n4)
{
    int i = blockIdx.x * blockDim.x + threadIdx.x;
    if (i < n4) {
        float4 v = reinterpret_cast<const float4*>(in)[i];
        __half2 h0 = __floats2half2_rn(v.x, v.y);
        __half2 h1 = __floats2half2_rn(v.z, v.w);
        uint2 r;
        r.x = *reinterpret_cast<uint32_t*>(&h0);
        r.y = *reinterpret_cast<uint32_t*>(&h1);
        reinterpret_cast<uint2*>(out)[i] = r;
    }
}

// ----------------------------------------------------------------------------
// fp16 GEMM NT: C[M,N] = A[M,512] * B[N,512]^T (+bias)
// ----------------------------------------------------------------------------
#define BM 128
#define BN 128
#define BKH 32
#define NSTAGE 5
#define NTT (KK / BKH)
#define RSTRH 40
#define STG_HALVES (128 * RSTRH)
#define STG_BYTES (2 * STG_HALVES * 2)
#define GEMM_SMEM_BYTES (NSTAGE * STG_BYTES)  // 102400

template <bool HALF_OUT>
__global__ __launch_bounds__(256, 2)
void gemm_f16(const __half* __restrict__ A, const __half* __restrict__ Bw,
              const float* __restrict__ bias, void* __restrict__ Cv, int N)
{
    extern __shared__ __align__(16) char smem[];
    const int tid  = threadIdx.x;
    const int w    = tid >> 5;
    const int lane = tid & 31;
    const int row0 = blockIdx.y * BM;
    const int col0 = blockIdx.x * BN;
    const int warpM = (w & 3) * 32;
    const int warpN = (w >> 2) * 64;

    const uint32_t sb = smem_u32(smem);
    const int chunk = tid & 3;
    const int lrow  = tid >> 2;

    const __half* Arow0 = A  + (size_t)(row0 + lrow) * KK + chunk * 8;
    const __half* Arow1 = A  + (size_t)(row0 + lrow + 64) * KK + chunk * 8;
    const __half* Brow0 = Bw + (size_t)(col0 + lrow) * KK + chunk * 8;
    const __half* Brow1 = Bw + (size_t)(col0 + lrow + 64) * KK + chunk * 8;
    const uint32_t soA0 = (uint32_t)(lrow * RSTRH + chunk * 8) * 2u;
    const uint32_t soA1 = (uint32_t)((lrow + 64) * RSTRH + chunk * 8) * 2u;
    const uint32_t bofs = (uint32_t)STG_HALVES * 2u;

    const int lm = lane >> 3;
    const int li = lane & 7;
    uint32_t aoff[2], boff[4];
    #pragma unroll
    for (int mt = 0; mt < 2; ++mt) {
        const int r = warpM + mt * 16 + (lm & 1) * 8 + li;
        aoff[mt] = (uint32_t)(r * RSTRH) * 2u + (uint32_t)(lm >> 1) * 16u;
    }
    #pragma unroll
    for (int p = 0; p < 4; ++p) {
        const int r = warpN + p * 16 + (lm >> 1) * 8 + li;
        boff[p] = (uint32_t)(r * RSTRH) * 2u + (uint32_t)(lm & 1) * 16u + bofs;
    }

    float acc[2][8][4];
    #pragma unroll
    for (int mt = 0; mt < 2; ++mt)
        #pragma unroll
        for (int nt = 0; nt < 8; ++nt)
            #pragma unroll
            for (int i = 0; i < 4; ++i) acc[mt][nt][i] = 0.f;

    #pragma unroll
    for (int p = 0; p < NSTAGE - 1; ++p) {
        const uint32_t st = sb + (uint32_t)p * STG_BYTES;
        const int koff = p * BKH;
        cp16(st + soA0, Arow0 + koff);
        cp16(st + soA1, Arow1 + koff);
        cp16(st + bofs + soA0, Brow0 + koff);
        cp16(st + bofs + soA1, Brow1 + koff);
        CP_COMMIT();
    }

    const int qrow = lane >> 2;
    const int qcol = lane & 3;

    for (int kt = 0; kt < NTT; ++kt) {
        if (kt < NTT - 1) { CP_WAIT(NSTAGE - 2); } else { CP_WAIT(0); }
        __syncthreads();

        if (kt + NSTAGE - 1 < NTT) {
            const int s = (kt + NSTAGE - 1) % NSTAGE;
            const uint32_t st = sb + (uint32_t)s * STG_BYTES;
            const int koff = (kt + NSTAGE - 1) * BKH;
            cp16(st + soA0, Arow0 + koff);
            cp16(st + soA1, Arow1 + koff);
            cp16(st + bofs + soA0, Brow0 + koff);
            cp16(st + bofs + soA1, Brow1 + koff);
            CP_COMMIT();
        }

        const uint32_t stg = sb + (uint32_t)(kt % NSTAGE) * STG_BYTES;

        #pragma unroll
        for (int ks = 0; ks < 2; ++ks) {
            const uint32_t kb = (uint32_t)(ks * 16 * 2);
            uint32_t af[2][4], bf[4][4];
            #pragma unroll
            for (int mt = 0; mt < 2; ++mt)
                LDSM_X4(af[mt], stg + aoff[mt] + kb);
            #pragma unroll
            for (int p = 0; p < 4; ++p)
                LDSM_X4(bf[p], stg + boff[p] + kb);

            #pragma unroll
            for (int mt = 0; mt < 2; ++mt)
                #pragma unroll
                for (int nt = 0; nt < 8; ++nt) {
                    const int p = nt >> 1;
                    const int o = (nt & 1) * 2;
                    mma_f16(acc[mt][nt][0], acc[mt][nt][1],
                            acc[mt][nt][2], acc[mt][nt][3],
                            af[mt][0], af[mt][1], af[mt][2], af[mt][3],
                            bf[p][o], bf[p][o + 1]);
                }
        }
    }

    #pragma unroll
    for (int mt = 0; mt < 2; ++mt) {
        const int r0 = row0 + warpM + mt * 16 + qrow;
        #pragma unroll
        for (int nt = 0; nt < 8; ++nt) {
            const int c = col0 + warpN + nt * 8 + qcol * 2;
            if (HALF_OUT) {
                __half* C = (__half*)Cv;
                __half2 h0 = __floats2half2_rn(acc[mt][nt][0], acc[mt][nt][1]);
                __half2 h1 = __floats2half2_rn(acc[mt][nt][2], acc[mt][nt][3]);
                *reinterpret_cast<__half2*>(C + (size_t)r0 * N + c) = h0;
                *reinterpret_cast<__half2*>(C + (size_t)(r0 + 8) * N + c) = h1;
            } else {
                float* C = (float*)Cv;
                float2 v0 = make_float2(acc[mt][nt][0], acc[mt][nt][1]);
                float2 v1 = make_float2(acc[mt][nt][2], acc[mt][nt][3]);
                if (bias) {
                    const float b0 = bias[c], b1 = bias[c + 1];
                    v0.x += b0; v0.y += b1;
                    v1.x += b0; v1.y += b1;
                }
                *reinterpret_cast<float2*>(C + (size_t)r0 * N + c) = v0;
                *reinterpret_cast<float2*>(C + (size_t)(r0 + 8) * N + c) = v1;
            }
        }
    }
}

// ----------------------------------------------------------------------------
// Stripe attention + LePE. uint4 q/k loads; v staged as 30-pixel halo tile in
// smem (zero-filled OOB = conv 'SAME'), serving both P@V and the 9 LePE taps.
// ----------------------------------------------------------------------------
#define SROW 264      // float row stride for qs/ks
#define VROW 264      // half row stride for halo
#define NHALO 30

__global__ __launch_bounds__(256) void stripe_attn_kernel(
    const __half* __restrict__ qkv,
    const float* __restrict__ lepe_h,
    const float* __restrict__ lepe_v,
    __half* __restrict__ out)
{
    __shared__ float  qs[SS * SROW];
    __shared__ float  ks[SS * SROW];
    __shared__ __half vh[NHALO * VROW];
    __shared__ float  Ssm[8][64];

    const int blk  = blockIdx.x;
    const int axis = (blk >= 4096) ? 1 : 0;
    const int wb   = blk & 4095;
    const int tid  = threadIdx.x;
    const int warp = tid >> 5;
    const int lane = tid & 31;

    int b = wb >> 9;
    int rem = wb & 511;
    int h0, w0, dh, dw;
    if (axis == 0) {
        int s = rem >> 6;
        int ww = rem & 63;
        h0 = s * SS; w0 = ww; dh = 1; dw = 0;
    } else {
        int hh = rem >> 3;
        int s = rem & 7;
        h0 = hh; w0 = s * SS; dh = 0; dw = 1;
    }
    const int cbase = axis * HALF;
    const float* lw = axis ? lepe_v : lepe_h;

    // halo geometry: axis0 -> 10 rows x 3 cols; axis1 -> 3 rows x 10 cols
    const int hcols   = axis ? 10 : 3;   // columns in halo grid
    const int istride = axis ? 1 : 3;    // halo idx step per window position
    const int sH      = axis ? 10 : 3;   // halo idx step per kh
    const int woff    = axis ? 11 : 4;   // halo idx of window position 0

    // ---- load q,k: 1 uint4 each per thread ----
    {
        const int i  = tid >> 5;
        const int c8 = (tid & 31) * 8;
        const int l = (h0 + dh * i) * Wc + (w0 + dw * i);
        const size_t base = ((size_t)(b * Lc + l)) * QKVN + cbase + c8;
        uint4 qv = *reinterpret_cast<const uint4*>(qkv + base);
        uint4 kv = *reinterpret_cast<const uint4*>(qkv + base + Cc);
        h8_to_f8(qv, &qs[i * SROW + c8]);
        h8_to_f8(kv, &ks[i * SROW + c8]);
    }

    // ---- load v halo: 30 pixels x 32 chunks = 960 uint4 over 256 threads ----
    for (int t = tid; t < NHALO * 32; t += 256) {
        const int pix   = t >> 5;
        const int chunk = (t & 31) * 8;
        const int r = pix / hcols;
        const int c = pix - r * hcols;
        const int hh = h0 - 1 + r;
        const int ww = w0 - 1 + c;
        uint4 v = make_uint4(0u, 0u, 0u, 0u);
        if (hh >= 0 && hh < Hc && ww >= 0 && ww < Wc) {
            const size_t vb = ((size_t)(b * Lc + hh * Wc + ww)) * QKVN
                            + 2 * Cc + cbase + chunk;
            v = *reinterpret_cast<const uint4*>(qkv + vb);
        }
        *reinterpret_cast<uint4*>(&vh[pix * VROW + chunk]) = v;
    }
    __syncthreads();

    const float inv_scale = 0.17677669529663687f;
    const int ch = warp * HD;

    // ---- S = q k^T / scale ----
    #pragma unroll
    for (int p = lane; p < 64; p += 32) {
        int i = p >> 3, j = p & 7;
        float acc = 0.f;
        #pragma unroll
        for (int d = 0; d < HD; ++d)
            acc += qs[i * SROW + ch + d] * ks[j * SROW + ch + d];
        Ssm[warp][p] = acc * inv_scale;
    }
    __syncwarp();

    // ---- softmax per row ----
    if (lane < 8) {
        int i = lane;
        float m = -INFINITY;
        #pragma unroll
        for (int j = 0; j < 8; ++j) m = fmaxf(m, Ssm[warp][i * 8 + j]);
        float e[8], sum = 0.f;
        #pragma unroll
        for (int j = 0; j < 8; ++j) { e[j] = __expf(Ssm[warp][i * 8 + j] - m); sum += e[j]; }
        float inv = 1.0f / sum;
        #pragma unroll
        for (int j = 0; j < 8; ++j) Ssm[warp][i * 8 + j] = e[j] * inv;
    }
    __syncwarp();

    // ---- out = P @ V + LePE(v), all reads from smem halo ----
    const int d = lane;
    float wl[9];
    #pragma unroll
    for (int t = 0; t < 9; ++t) wl[t] = lw[t * HALF + ch + d];

    // v window values (position j) as floats
    float vwin[8];
    #pragma unroll
    for (int j = 0; j < 8; ++j)
        vwin[j] = __half2float(vh[(j * istride + woff) * VROW + ch + d]);

    #pragma unroll
    for (int i = 0; i < SS; ++i) {
        float acc = 0.f;
        #pragma unroll
        for (int j = 0; j < 8; ++j)
            acc += Ssm[warp][i * 8 + j] * vwin[j];

        float lep = 0.f;
        #pragma unroll
        for (int kh = 0; kh < 3; ++kh)
            #pragma unroll
            for (int kw = 0; kw < 3; ++kw) {
                const int idx = i * istride + kh * sH + kw;
                lep = fmaf(__half2float(vh[idx * VROW + ch + d]),
                           wl[kh * 3 + kw], lep);
            }

        const int l = (h0 + dh * i) * Wc + (w0 + dw * i);
        out[((size_t)(b * Lc + l)) * Cc + cbase + ch + d] =
            __float2half_rn(acc + lep);
    }
}

// ----------------------------------------------------------------------------
// Launch.  Inputs: x, w_qkv, w_proj, b_proj, lepe_h_w, lepe_v_w, H, W
// ----------------------------------------------------------------------------
extern "C" void kernel_launch(void* const* d_in, const int* in_sizes, int n_in,
                              void* d_out, int out_size)
{
    const float* x       = (const float*)d_in[0];
    const float* w_qkv   = (const float*)d_in[1];
    const float* w_proj  = (const float*)d_in[2];
    const float* b_proj  = (const float*)d_in[3];
    const float* lepe_h  = (const float*)d_in[4];
    const float* lepe_v  = (const float*)d_in[5];
    float* out = (float*)d_out;

    void *p_qkvh, *p_attnh, *p_xh, *p_wqkvh, *p_wph;
    cudaGetSymbolAddress(&p_qkvh,  g_qkvh);
    cudaGetSymbolAddress(&p_attnh, g_attnh);
    cudaGetSymbolAddress(&p_xh,    g_xh);
    cudaGetSymbolAddress(&p_wqkvh, g_wqkvh);
    cudaGetSymbolAddress(&p_wph,   g_wph);
    __half* qkvh  = (__half*)p_qkvh;
    __half* attnh = (__half*)p_attnh;
    __half* xh    = (__half*)p_xh;
    __half* wqkvh = (__half*)p_wqkvh;
    __half* wph   = (__half*)p_wph;

    cudaFuncSetAttribute(gemm_f16<true>,
                         cudaFuncAttributeMaxDynamicSharedMemorySize,
                         GEMM_SMEM_BYTES);
    cudaFuncSetAttribute(gemm_f16<false>,
                         cudaFuncAttributeMaxDynamicSharedMemorySize,
                         GEMM_SMEM_BYTES);

    // 0) prepass: convert operands to fp16
    {
        int n4 = (Mrows * Cc) / 4;
        f2h_kernel<<<(n4 + 255) / 256, 256>>>(x, xh, n4);
        n4 = (QKVN * Cc) / 4;
        f2h_kernel<<<(n4 + 255) / 256, 256>>>(w_qkv, wqkvh, n4);
        n4 = (Cc * Cc) / 4;
        f2h_kernel<<<(n4 + 255) / 256, 256>>>(w_proj, wph, n4);
    }

    // 1) qkv = x @ w_qkv^T  (fp16 in, fp16 out)
    {
        dim3 grid(QKVN / BN, Mrows / BM);
        gemm_f16<true><<<grid, 256, GEMM_SMEM_BYTES>>>(xh, wqkvh, nullptr, qkvh, QKVN);
    }

    // 2) stripe attention (both halves) + LePE (fp16 in/out)
    stripe_attn_kernel<<<8192, 256>>>(qkvh, lepe_h, lepe_v, attnh);

    // 3) out = attn @ w_proj^T + b_proj  (fp16 in, fp32 out)
    {
        dim3 grid(Cc / BN, Mrows / BM);
        gemm_f16<false><<<grid, 256, GEMM_SMEM_BYTES>>>(attnh, wph, b_proj, out, Cc);
    }
}